// round 15
// baseline (speedup 1.0000x reference)
#include <cuda_runtime.h>
#include <cstdint>

// Problem constants (fixed by the reference)
#define BB 16
#define NN 8192
#define MM 2048
#define KK 32
#define CC 128

// out layout: [pts (B*M*K*3 floats)] ++ [features (B*M*K*C floats)]
//
// R12/R13 converged structure with ONE change: 256-bit vector memory ops
// (sm_100+ ld.global.nc.v8.f32 / st.global.v8.f32).
// One CTA per (b, m), 128 threads = 4 warps, 16 resident CTAs/SM.
//  - warp 0: normalized relative coords for all K=32 neighbors (lane = k)
//  - warp w owns consecutive rows {8w..8w+7}, processed 2 rows per
//    iteration: lanes 0-15 -> row k, lanes 16-31 -> row k+1; each lane
//    moves 32B with one v8 load + one v8 store (1024B per warp instr,
//    strict load->store interleave preserved).
__global__ __launch_bounds__(128, 16)
void knn_gather_norm_v14_kernel(const float* __restrict__ input,      // [B,N,C]
                                const float* __restrict__ points,     // [B,N,3]
                                const float* __restrict__ next_pts,   // [B,M,3]
                                const int*   __restrict__ indices,    // [B,M,K]
                                float* __restrict__ out_pts,          // [B,M,K,3]
                                float* __restrict__ out_feat)         // [B,M,K,C]
{
    const int bm = blockIdx.x;            // 0 .. B*M-1
    const int b  = bm / MM;

    __shared__ int sidx[KK];

    const int tid  = threadIdx.x;
    const int wid  = tid >> 5;
    const int lane = tid & 31;

    if (tid < KK) {
        sidx[tid] = indices[(size_t)bm * KK + tid];
    }
    __syncthreads();

    // ---- pts: warp 0, lane = neighbor k ----
    if (wid == 0) {
        const int k   = lane;
        const int idx = sidx[k];

        const float nx = __ldg(&next_pts[(size_t)bm * 3 + 0]);
        const float ny = __ldg(&next_pts[(size_t)bm * 3 + 1]);
        const float nz = __ldg(&next_pts[(size_t)bm * 3 + 2]);

        const float* p = points + ((size_t)b * NN + (size_t)idx) * 3;
        const float dx = __ldg(&p[0]) - nx;
        const float dy = __ldg(&p[1]) - ny;
        const float dz = __ldg(&p[2]) - nz;

        float mx = dx * dx + dy * dy + dz * dz;
        #pragma unroll
        for (int o = 16; o > 0; o >>= 1)
            mx = fmaxf(mx, __shfl_xor_sync(0xffffffffu, mx, o));

        float maxi = sqrtf(mx);
        if (maxi == 0.0f) maxi = 1.0f;
        const float inv = 1.0f / maxi;

        float* o = out_pts + ((size_t)bm * KK + (size_t)k) * 3;
        o[0] = dx * inv;
        o[1] = dy * inv;
        o[2] = dz * inv;
    }

    // ---- features: warp wid owns rows {8w..8w+7}, 2 rows / iteration ----
    const int   half  = lane >> 4;         // 0: rows k, 1: rows k+1
    const int   sub   = lane & 15;         // 16 lanes x 32B = 512B row
    const float* __restrict__ in_b = input + (size_t)b * NN * CC;
    float* __restrict__ of = out_feat + (size_t)bm * KK * CC;

    #pragma unroll
    for (int j = 0; j < 4; ++j) {
        const int k   = 8 * wid + 2 * j + half;
        const int idx = sidx[k];

        const float* src = in_b + (size_t)idx * CC + sub * 8;
        float*       dst = of   + (size_t)k   * CC + sub * 8;

        float r0, r1, r2, r3, r4, r5, r6, r7;
        asm volatile(
            "ld.global.nc.v8.f32 {%0,%1,%2,%3,%4,%5,%6,%7}, [%8];"
            : "=f"(r0), "=f"(r1), "=f"(r2), "=f"(r3),
              "=f"(r4), "=f"(r5), "=f"(r6), "=f"(r7)
            : "l"(src));
        asm volatile(
            "st.global.v8.f32 [%0], {%1,%2,%3,%4,%5,%6,%7,%8};"
            :: "l"(dst),
               "f"(r0), "f"(r1), "f"(r2), "f"(r3),
               "f"(r4), "f"(r5), "f"(r6), "f"(r7)
            : "memory");
    }
}

extern "C" void kernel_launch(void* const* d_in, const int* in_sizes, int n_in,
                              void* d_out, int out_size)
{
    const float* input    = (const float*)d_in[0];  // [B,N,C]
    const float* points   = (const float*)d_in[1];  // [B,N,3]
    const float* next_pts = (const float*)d_in[2];  // [B,M,3]
    const int*   indices  = (const int*)  d_in[3];  // [B,M,K]

    float* out_pts  = (float*)d_out;                         // B*M*K*3
    float* out_feat = out_pts + (size_t)BB * MM * KK * 3;    // B*M*K*C

    const int grid = BB * MM;   // 32768 CTAs
    knn_gather_norm_v14_kernel<<<grid, 128>>>(input, points, next_pts, indices,
                                              out_pts, out_feat);
}